// round 2
// baseline (speedup 1.0000x reference)
#include <cuda_runtime.h>
#include <cstdint>

#define T_STEPS   256
#define BATCH     32
#define N_INP     28
#define N_HID     1024
#define N_OUT     10
#define NCTA      128
#define ROWS_CTA  8          // 1024 / 128
#define TPB       256
#define TWO_PI_F  6.283185307179586f

// ---------------- device globals (scratch; no allocations allowed) ----------
__device__ float g_inp[T_STEPS * N_HID * BATCH];          // [t][h][b]  (Wi x + Wi_b + omega)
__device__ __align__(256) float g_X[2][N_HID][64];        // [buf][j][n] n<32: cos_b, n>=32: sin_b
__device__ float g_state[BATCH * N_HID];                  // [b][h]
__device__ unsigned g_cnt;
__device__ unsigned g_gen;

// packed f32x2 FMA: acc += a * b   (two fp32 lanes per instruction)
#define FMA2(acc, a, b) \
    asm("fma.rn.f32x2 %0, %1, %2, %0;" : "+l"(acc) : "l"(a), "l"(b))

// ---------------- grid-wide barrier (sense via generation counter) ----------
__device__ __forceinline__ void grid_barrier(int tid, unsigned target) {
    __syncthreads();
    if (tid == 0) {
        unsigned old;
        asm volatile("atom.release.gpu.global.add.u32 %0, [%1], %2;"
                     : "=r"(old) : "l"(&g_cnt), "r"(1u) : "memory");
        if (old == NCTA - 1) {
            asm volatile("st.global.relaxed.gpu.u32 [%0], %1;"
                         :: "l"(&g_cnt), "r"(0u) : "memory");
            asm volatile("st.global.release.gpu.u32 [%0], %1;"
                         :: "l"(&g_gen), "r"(target) : "memory");
        } else {
            unsigned gv;
            do {
                asm volatile("ld.global.acquire.gpu.u32 %0, [%1];"
                             : "=r"(gv) : "l"(&g_gen) : "memory");
            } while (gv < target);
        }
    }
    __syncthreads();
}

// ---------------- kernel A: input projection + barrier reset ----------------
// g_inp[t][h][b] = Wi_b[h] + omega[h] + sum_k Wi_w[h][k] * x[t][b][k]
__global__ void prep_kernel(const float* __restrict__ x,
                            const float* __restrict__ Wi_w,
                            const float* __restrict__ Wi_b,
                            const float* __restrict__ omega) {
    __shared__ float xs[BATCH * N_INP];
    int t  = blockIdx.y;
    int hg = blockIdx.x;                 // 8 h per block
    int tid = threadIdx.x;
    if (t == 0 && hg == 0 && tid == 0) { g_cnt = 0; g_gen = 0; }
    for (int i = tid; i < BATCH * N_INP; i += TPB)
        xs[i] = x[t * BATCH * N_INP + i];
    __syncthreads();
    int hh = tid >> 5;
    int b  = tid & 31;
    int h  = hg * 8 + hh;
    float acc = Wi_b[h] + omega[h];
    const float* wr = Wi_w + h * N_INP;
#pragma unroll
    for (int k = 0; k < N_INP; k++)
        acc = fmaf(wr[k], xs[b * N_INP + k], acc);
    g_inp[(t * N_HID + h) * BATCH + b] = acc;
}

// ---------------- kernel B: persistent scan over T -------------------------
// SMEM: [0,64K) Wh pairs [j][8 u64] ; [64K,80K) red[8][512] ; [80K,82K) fin[512]
extern __shared__ unsigned char smem_raw[];

__global__ void __launch_bounds__(TPB, 1)
step_kernel(const float* __restrict__ Wh) {
    unsigned long long* wh64 = (unsigned long long*)smem_raw;        // [j*8 + r]
    const ulonglong2*   wh2  = (const ulonglong2*)smem_raw;          // [j*4 + rg]
    float* red = (float*)(smem_raw + 65536);                         // [w*512 + row*64 + n]
    float* fin = (float*)(smem_raw + 65536 + 16384);                 // [row*64 + n]

    int tid  = threadIdx.x;
    int cta  = blockIdx.x;
    int w    = tid >> 5;
    int lane = tid & 31;
    int rg   = lane >> 3;       // row-group (2 rows each)
    int ng   = lane & 7;        // n-group (8 n each)
    int i0   = cta * ROWS_CTA;

    // Wh rows -> SMEM, each value duplicated into a packed pair
    for (int idx = tid; idx < ROWS_CTA * N_HID; idx += TPB) {
        int r = idx >> 10;
        int j = idx & (N_HID - 1);
        unsigned vb = __float_as_uint(Wh[(i0 + r) * N_HID + j]);
        wh64[j * 8 + r] = ((unsigned long long)vb << 32) | vb;
    }
    // init state = 0, X[0] = (cos=1, sin=0) for own rows
    {
        int il = tid >> 5, b = tid & 31;
        int ig = i0 + il;
        g_state[b * N_HID + ig] = 0.f;
        g_X[0][ig][b]      = 1.f;
        g_X[0][ig][32 + b] = 0.f;
    }
    grid_barrier(tid, 1);

    for (int t = 0; t < T_STEPS; t++) {
        int cur = t & 1, nxt = cur ^ 1;
        const ulonglong2* Xv = (const ulonglong2*)&g_X[cur][0][0];   // 16 per j-row

        // ---- GEMM: warp w owns K-slice [128w, 128w+128) ----
        unsigned long long a00=0,a01=0,a02=0,a03=0,a10=0,a11=0,a12=0,a13=0;
        const int j0 = w * 128;
        const ulonglong2* whp_p = wh2 + (size_t)j0 * 4 + rg;
        const ulonglong2* x_p   = Xv  + (size_t)j0 * 16 + ng * 2;
#pragma unroll 8
        for (int jj = 0; jj < 128; jj++) {
            ulonglong2 whp = whp_p[jj * 4];                 // rows 2rg, 2rg+1 (paired)
            ulonglong2 xa  = __ldcg(x_p + jj * 16);         // n = 8ng .. 8ng+3
            ulonglong2 xb  = __ldcg(x_p + jj * 16 + 1);     // n = 8ng+4 .. 8ng+7
            FMA2(a00, whp.x, xa.x); FMA2(a01, whp.x, xa.y);
            FMA2(a02, whp.x, xb.x); FMA2(a03, whp.x, xb.y);
            FMA2(a10, whp.y, xa.x); FMA2(a11, whp.y, xa.y);
            FMA2(a12, whp.y, xb.x); FMA2(a13, whp.y, xb.y);
        }
        // ---- partials to SMEM ----
        {
            unsigned long long* rw = (unsigned long long*)(red + w * 512);
            int r0 = 2 * rg;
            rw[r0 * 32 + ng * 4 + 0] = a00; rw[r0 * 32 + ng * 4 + 1] = a01;
            rw[r0 * 32 + ng * 4 + 2] = a02; rw[r0 * 32 + ng * 4 + 3] = a03;
            int r1 = r0 + 1;
            rw[r1 * 32 + ng * 4 + 0] = a10; rw[r1 * 32 + ng * 4 + 1] = a11;
            rw[r1 * 32 + ng * 4 + 2] = a12; rw[r1 * 32 + ng * 4 + 3] = a13;
        }
        __syncthreads();
        // ---- reduce across the 8 K-slices ----
        for (int o = tid; o < 512; o += TPB) {
            float s = red[o];
#pragma unroll
            for (int ww = 1; ww < 8; ww++) s += red[ww * 512 + o];
            fin[o] = s;
        }
        __syncthreads();
        // ---- combine + state update + next-step cos/sin ----
        {
            int il = tid >> 5, b = tid & 31;
            int ig = i0 + il;
            float Cc = fin[il * 64 + b];
            float Cs = fin[il * 64 + 32 + b];
            float ci = g_X[cur][ig][b];
            float si = g_X[cur][ig][32 + b];
            float coupling = si * Cc - ci * Cs;
            float st = g_state[b * N_HID + ig];
            float v  = coupling + g_inp[(t * N_HID + ig) * BATCH + b] + st;
            float r  = fmodf(v, TWO_PI_F);
            if (r < 0.f) r += TWO_PI_F;                 // == jnp.remainder(v, 2pi)
            g_state[b * N_HID + ig] = r;
            float sn, cn;
            sincosf(r, &sn, &cn);
            g_X[nxt][ig][b]      = cn;
            g_X[nxt][ig][32 + b] = sn;
        }
        grid_barrier(tid, (unsigned)(t + 2));
    }
}

// ---------------- kernel C: readout  out[b][o] = state[b]·W_out[o] + b_out --
__global__ void readout_kernel(const float* __restrict__ W_out,
                               const float* __restrict__ b_out,
                               float* __restrict__ out) {
    int tid = threadIdx.x;
    if (tid >= BATCH * N_OUT) return;
    int b = tid / N_OUT, o = tid % N_OUT;
    const float* sr = g_state + b * N_HID;
    const float* wr = W_out + o * N_HID;
    float a0 = 0.f, a1 = 0.f, a2 = 0.f, a3 = 0.f;
#pragma unroll 8
    for (int h = 0; h < N_HID; h += 4) {
        a0 = fmaf(sr[h + 0], wr[h + 0], a0);
        a1 = fmaf(sr[h + 1], wr[h + 1], a1);
        a2 = fmaf(sr[h + 2], wr[h + 2], a2);
        a3 = fmaf(sr[h + 3], wr[h + 3], a3);
    }
    out[b * N_OUT + o] = ((a0 + a1) + (a2 + a3)) + b_out[o];
}

// ---------------- launch ----------------------------------------------------
extern "C" void kernel_launch(void* const* d_in, const int* in_sizes, int n_in,
                              void* d_out, int out_size) {
    const float* x     = (const float*)d_in[0];
    const float* Wi_w  = (const float*)d_in[1];
    const float* Wi_b  = (const float*)d_in[2];
    const float* Wh    = (const float*)d_in[3];
    const float* omega = (const float*)d_in[4];
    const float* W_out = (const float*)d_in[5];
    const float* b_out = (const float*)d_in[6];
    float* out = (float*)d_out;

    const int SMEM_BYTES = 65536 + 16384 + 2048;   // 83968
    cudaFuncSetAttribute(step_kernel,
                         cudaFuncAttributeMaxDynamicSharedMemorySize, SMEM_BYTES);

    prep_kernel<<<dim3(N_HID / 8, T_STEPS), TPB>>>(x, Wi_w, Wi_b, omega);
    step_kernel<<<NCTA, TPB, SMEM_BYTES>>>(Wh);
    readout_kernel<<<1, 384>>>(W_out, b_out, out);
}

// round 3
// speedup vs baseline: 1.0243x; 1.0243x over previous
#include <cuda_runtime.h>
#include <cstdint>

#define T_STEPS   256
#define BATCH     32
#define N_INP     28
#define N_HID     1024
#define N_OUT     10
#define NCTA      128
#define ROWS_CTA  8          // 1024 / 128
#define TPB       512        // 16 warps: warp w owns K-slice of 64 j
#define TWO_PI_F  6.283185307179586f

// ---------------- device globals (scratch; no allocations allowed) ----------
__device__ float g_inp[T_STEPS * N_HID * BATCH];          // [t][h][b]
__device__ __align__(256) float g_X[2][N_HID][64];        // [buf][j][n] n<32: cos_b, n>=32: sin_b
__device__ float g_state[BATCH * N_HID];                  // [b][h]
__device__ unsigned g_flags[NCTA * 8];                    // 32B-spread arrival flags

// packed f32x2 FMA: acc += a * b   (two fp32 lanes per instruction)
#define FMA2(acc, a, b) \
    asm("fma.rn.f32x2 %0, %1, %2, %0;" : "+l"(acc) : "l"(a), "l"(b))

// ---------------- grid barrier: per-CTA flag + distributed poll -------------
__device__ __forceinline__ void grid_barrier(int tid, int cta, unsigned target) {
    __syncthreads();                       // all CTA stores done before publish
    if (tid < 32) {
        if (tid == 0) {
            asm volatile("st.global.release.gpu.u32 [%0], %1;"
                         :: "l"(&g_flags[cta * 8]), "r"(target) : "memory");
        }
        const unsigned* p0 = &g_flags[(tid +  0) * 8];
        const unsigned* p1 = &g_flags[(tid + 32) * 8];
        const unsigned* p2 = &g_flags[(tid + 64) * 8];
        const unsigned* p3 = &g_flags[(tid + 96) * 8];
        unsigned f0, f1, f2, f3;
        bool pending;
        do {
            asm volatile("ld.global.acquire.gpu.u32 %0, [%1];" : "=r"(f0) : "l"(p0) : "memory");
            asm volatile("ld.global.acquire.gpu.u32 %0, [%1];" : "=r"(f1) : "l"(p1) : "memory");
            asm volatile("ld.global.acquire.gpu.u32 %0, [%1];" : "=r"(f2) : "l"(p2) : "memory");
            asm volatile("ld.global.acquire.gpu.u32 %0, [%1];" : "=r"(f3) : "l"(p3) : "memory");
            pending = (f0 < target) | (f1 < target) | (f2 < target) | (f3 < target);
        } while (__any_sync(0xFFFFFFFFu, pending));
    }
    __syncthreads();                       // broadcast release to whole CTA
}

// ---------------- kernel A: input projection + global init -----------------
// One block per timestep. Warp w covers h in [128w, 128w+128), lane = b.
// g_inp[t][h][b] = Wi_b[h] + omega[h] + sum_k Wi_w[h][k] * x[t][b][k]
__global__ void __launch_bounds__(256)
prep_kernel(const float* __restrict__ x,
            const float* __restrict__ Wi_w,
            const float* __restrict__ Wi_b,
            const float* __restrict__ omega) {
    int t   = blockIdx.x;
    int tid = threadIdx.x;
    int w   = tid >> 5;
    int b   = tid & 31;

    if (t == 0 && tid < NCTA) g_flags[tid * 8] = 0;   // reset barrier flags

    // per-lane x row -> registers (28 floats as 7 float4)
    float4 xq[7];
    const float4* xrow = (const float4*)(x + (size_t)t * BATCH * N_INP + b * N_INP);
#pragma unroll
    for (int q = 0; q < 7; q++) xq[q] = xrow[q];

    int h0 = w * 128;
    for (int hh = 0; hh < 128; hh++) {
        int h = h0 + hh;
        const float4* wr = (const float4*)(Wi_w + (size_t)h * N_INP);
        float acc = __ldg(Wi_b + h) + __ldg(omega + h);
#pragma unroll
        for (int q = 0; q < 7; q++) {
            float4 wv = __ldg(wr + q);
            acc = fmaf(wv.x, xq[q].x, acc);
            acc = fmaf(wv.y, xq[q].y, acc);
            acc = fmaf(wv.z, xq[q].z, acc);
            acc = fmaf(wv.w, xq[q].w, acc);
        }
        g_inp[((size_t)t * N_HID + h) * BATCH + b] = acc;
    }
}

// ---------------- kernel B: persistent scan over T -------------------------
// SMEM: [0,64K) Wh pairs [j][8 u64] ; [64K,96K) red[16][512]
extern __shared__ unsigned char smem_raw[];

__global__ void __launch_bounds__(TPB, 1)
step_kernel(const float* __restrict__ Wh) {
    unsigned long long* wh64 = (unsigned long long*)smem_raw;        // [j*8 + r]
    const ulonglong2*   wh2  = (const ulonglong2*)smem_raw;          // [j*4 + rg]
    float* red = (float*)(smem_raw + 65536);                         // [w*512 + row*64 + n]

    int tid  = threadIdx.x;
    int cta  = blockIdx.x;
    int w    = tid >> 5;        // 0..15
    int lane = tid & 31;
    int rg   = lane >> 3;       // row-group (2 rows each)
    int ng   = lane & 7;        // n-group (8 n each)
    int i0   = cta * ROWS_CTA;

    // Wh rows -> SMEM, each value duplicated into a packed pair
    for (int idx = tid; idx < ROWS_CTA * N_HID; idx += TPB) {
        int r = idx >> 10;
        int j = idx & (N_HID - 1);
        unsigned vb = __float_as_uint(Wh[(size_t)(i0 + r) * N_HID + j]);
        wh64[j * 8 + r] = ((unsigned long long)vb << 32) | vb;
    }

    // combine-thread registers (tid<256 owns output (row il, batch b))
    int il = tid >> 5;          // reuse only when tid<256 (il<8)
    int b  = tid & 31;
    int ig = i0 + (il & 7);
    float st = 0.f, ci = 1.f, si = 0.f;
    if (tid < 256) {            // init X[0] for own rows
        g_X[0][ig][b]      = 1.f;
        g_X[0][ig][32 + b] = 0.f;
    }
    grid_barrier(tid, cta, 1);

    const int j0 = w * 64;
    const ulonglong2* whp_p = wh2 + (size_t)j0 * 4 + rg;

    for (int t = 0; t < T_STEPS; t++) {
        int cur = t & 1, nxt = cur ^ 1;

        // prefetch this step's input term early
        float inp_v = 0.f;
        if (tid < 256)
            inp_v = __ldcg(&g_inp[((size_t)t * N_HID + ig) * BATCH + b]);

        // ---- GEMM: warp w owns K-slice [64w, 64w+64) ----
        const ulonglong2* x_p = (const ulonglong2*)&g_X[cur][0][0]
                                + (size_t)j0 * 16 + ng * 2;
        unsigned long long a00=0,a01=0,a02=0,a03=0,a10=0,a11=0,a12=0,a13=0;
#pragma unroll 8
        for (int jj = 0; jj < 64; jj++) {
            ulonglong2 whp = whp_p[jj * 4];                 // rows 2rg, 2rg+1 (paired)
            ulonglong2 xa  = __ldcg(x_p + jj * 16);         // n = 8ng .. 8ng+3
            ulonglong2 xb  = __ldcg(x_p + jj * 16 + 1);     // n = 8ng+4 .. 8ng+7
            FMA2(a00, whp.x, xa.x); FMA2(a01, whp.x, xa.y);
            FMA2(a02, whp.x, xb.x); FMA2(a03, whp.x, xb.y);
            FMA2(a10, whp.y, xa.x); FMA2(a11, whp.y, xa.y);
            FMA2(a12, whp.y, xb.x); FMA2(a13, whp.y, xb.y);
        }
        // ---- partials to SMEM ----
        {
            unsigned long long* rw = (unsigned long long*)(red + w * 512);
            int r0 = 2 * rg;
            rw[r0 * 32 + ng * 4 + 0] = a00; rw[r0 * 32 + ng * 4 + 1] = a01;
            rw[r0 * 32 + ng * 4 + 2] = a02; rw[r0 * 32 + ng * 4 + 3] = a03;
            int r1 = r0 + 1;
            rw[r1 * 32 + ng * 4 + 0] = a10; rw[r1 * 32 + ng * 4 + 1] = a11;
            rw[r1 * 32 + ng * 4 + 2] = a12; rw[r1 * 32 + ng * 4 + 3] = a13;
        }
        __syncthreads();
        // ---- fused reduce + combine + state update + next cos/sin ----
        if (tid < 256) {
            int o1 = il * 64 + b;           // cos column
            int o2 = o1 + 32;               // sin column
            float Cc = 0.f, Cs = 0.f;
#pragma unroll
            for (int ww = 0; ww < 16; ww++) {
                Cc += red[ww * 512 + o1];
                Cs += red[ww * 512 + o2];
            }
            float coupling = si * Cc - ci * Cs;
            float v  = coupling + inp_v + st;
            float r  = fmodf(v, TWO_PI_F);
            if (r < 0.f) r += TWO_PI_F;     // == jnp.remainder(v, 2pi)
            st = r;
            float sn, cn;
            sincosf(r, &sn, &cn);
            ci = cn; si = sn;
            g_X[nxt][ig][b]      = cn;
            g_X[nxt][ig][32 + b] = sn;
        }
        grid_barrier(tid, cta, (unsigned)(t + 2));
    }
    if (tid < 256) g_state[b * N_HID + ig] = st;
}

// ---------------- kernel C: readout  out[b][o] = state[b]·W_out[o] + b_out --
__global__ void readout_kernel(const float* __restrict__ W_out,
                               const float* __restrict__ b_out,
                               float* __restrict__ out) {
    int tid = threadIdx.x;
    if (tid >= BATCH * N_OUT) return;
    int b = tid / N_OUT, o = tid % N_OUT;
    const float* sr = g_state + b * N_HID;
    const float* wr = W_out + o * N_HID;
    float a0 = 0.f, a1 = 0.f, a2 = 0.f, a3 = 0.f;
#pragma unroll 8
    for (int h = 0; h < N_HID; h += 4) {
        a0 = fmaf(sr[h + 0], wr[h + 0], a0);
        a1 = fmaf(sr[h + 1], wr[h + 1], a1);
        a2 = fmaf(sr[h + 2], wr[h + 2], a2);
        a3 = fmaf(sr[h + 3], wr[h + 3], a3);
    }
    out[b * N_OUT + o] = ((a0 + a1) + (a2 + a3)) + b_out[o];
}

// ---------------- launch ----------------------------------------------------
extern "C" void kernel_launch(void* const* d_in, const int* in_sizes, int n_in,
                              void* d_out, int out_size) {
    const float* x     = (const float*)d_in[0];
    const float* Wi_w  = (const float*)d_in[1];
    const float* Wi_b  = (const float*)d_in[2];
    const float* Wh    = (const float*)d_in[3];
    const float* omega = (const float*)d_in[4];
    const float* W_out = (const float*)d_in[5];
    const float* b_out = (const float*)d_in[6];
    float* out = (float*)d_out;

    const int SMEM_BYTES = 65536 + 32768;   // 98304
    cudaFuncSetAttribute(step_kernel,
                         cudaFuncAttributeMaxDynamicSharedMemorySize, SMEM_BYTES);

    prep_kernel<<<T_STEPS, 256>>>(x, Wi_w, Wi_b, omega);
    step_kernel<<<NCTA, TPB, SMEM_BYTES>>>(Wh);
    readout_kernel<<<1, 384>>>(W_out, b_out, out);
}

// round 5
// speedup vs baseline: 1.5720x; 1.5347x over previous
#include <cuda_runtime.h>
#include <cstdint>

#define T_STEPS   256
#define BATCH     32
#define N_INP     28
#define N_HID     1024
#define N_OUT     10
#define NCTA      128
#define ROWS_CTA  8          // 1024 / 128
#define TPB       512        // 16 warps: warp w owns K-slice of 64 j
#define TWO_PI_F  6.283185307179586f

typedef unsigned long long u64;

// ---------------- device globals ----------------
__device__ float g_inp[T_STEPS * N_HID * BATCH];            // [t][h][b]
__device__ __align__(256) u64 gX64[2][N_HID][BATCH];        // [buf][j][b] = pack(cos, sin)
__device__ unsigned g_flags[NCTA * 8];                      // 32B-spread arrival flags
__device__ float g_rout[BATCH * N_OUT * NCTA];              // readout partials [(b*10+o)*128 + cta]

// packed f32x2 ops
#define FMA2(acc, a, b) \
    asm("fma.rn.f32x2 %0, %1, %2, %0;" : "+l"(acc) : "l"(a), "l"(b))
#define ADD2(acc, b) \
    asm("add.rn.f32x2 %0, %0, %1;" : "+l"(acc) : "l"(b))

__device__ __forceinline__ u64 pack2(float lo, float hi) {
    u64 r;
    asm("mov.b64 %0, {%1, %2};" : "=l"(r) : "f"(lo), "f"(hi));
    return r;
}
__device__ __forceinline__ float lo32(u64 v) { return __uint_as_float((unsigned)v); }
__device__ __forceinline__ float hi32(u64 v) { return __uint_as_float((unsigned)(v >> 32)); }

// ---------------- grid barrier: per-CTA flag + distributed poll -------------
__device__ __forceinline__ void grid_barrier(int tid, int cta, unsigned target) {
    __syncthreads();
    if (tid < 32) {
        if (tid == 0) {
            asm volatile("st.global.release.gpu.u32 [%0], %1;"
                         :: "l"(&g_flags[cta * 8]), "r"(target) : "memory");
        }
        const unsigned* p0 = &g_flags[(tid +  0) * 8];
        const unsigned* p1 = &g_flags[(tid + 32) * 8];
        const unsigned* p2 = &g_flags[(tid + 64) * 8];
        const unsigned* p3 = &g_flags[(tid + 96) * 8];
        unsigned f0, f1, f2, f3;
        bool pending;
        do {
            asm volatile("ld.global.acquire.gpu.u32 %0, [%1];" : "=r"(f0) : "l"(p0) : "memory");
            asm volatile("ld.global.acquire.gpu.u32 %0, [%1];" : "=r"(f1) : "l"(p1) : "memory");
            asm volatile("ld.global.acquire.gpu.u32 %0, [%1];" : "=r"(f2) : "l"(p2) : "memory");
            asm volatile("ld.global.acquire.gpu.u32 %0, [%1];" : "=r"(f3) : "l"(p3) : "memory");
            pending = (f0 < target) | (f1 < target) | (f2 < target) | (f3 < target);
        } while (__any_sync(0xFFFFFFFFu, pending));
    }
    __syncthreads();
}

// ---------------- kernel A: input projection + flag reset -------------------
// grid (4, T): block covers h in [256*gx, 256*gx+256) for timestep gy.
__global__ void __launch_bounds__(256)
prep_kernel(const float* __restrict__ x,
            const float* __restrict__ Wi_w,
            const float* __restrict__ Wi_b,
            const float* __restrict__ omega) {
    int t   = blockIdx.y;
    int hg  = blockIdx.x;
    int tid = threadIdx.x;
    int w   = tid >> 5;
    int b   = tid & 31;

    if (t == 0 && hg == 0 && tid < NCTA) g_flags[tid * 8] = 0;

    float4 xq[7];
    const float4* xrow = (const float4*)(x + (size_t)t * BATCH * N_INP + b * N_INP);
#pragma unroll
    for (int q = 0; q < 7; q++) xq[q] = xrow[q];

    int h0 = hg * 256 + w * 32;
    for (int hh = 0; hh < 32; hh++) {
        int h = h0 + hh;
        const float4* wr = (const float4*)(Wi_w + (size_t)h * N_INP);
        float acc = __ldg(Wi_b + h) + __ldg(omega + h);
#pragma unroll
        for (int q = 0; q < 7; q++) {
            float4 wv = __ldg(wr + q);
            acc = fmaf(wv.x, xq[q].x, acc);
            acc = fmaf(wv.y, xq[q].y, acc);
            acc = fmaf(wv.z, xq[q].z, acc);
            acc = fmaf(wv.w, xq[q].w, acc);
        }
        g_inp[((size_t)t * N_HID + h) * BATCH + b] = acc;
    }
}

// ---------------- kernel B: persistent scan + fused readout -----------------
// SMEM: [0,64K) wh64[j][r] dup pairs ; [64K, +34816) red[(row*32+b)*17 + w] u64
extern __shared__ unsigned char smem_raw[];

__global__ void __launch_bounds__(TPB, 1)
step_kernel(const float* __restrict__ Wh,
            const float* __restrict__ W_out,
            const float* __restrict__ b_out,
            float* __restrict__ out) {
    u64* wh64 = (u64*)smem_raw;                          // [j*8 + r]
    const ulonglong2* wh2 = (const ulonglong2*)smem_raw; // [j*4 + k]
    u64* red = (u64*)(smem_raw + 65536);                 // [(r*32+b)*17 + w]

    int tid  = threadIdx.x;
    int cta  = blockIdx.x;
    int w    = tid >> 5;        // 0..15
    int lane = tid & 31;
    int jh   = lane >> 4;       // 0/1: which j of the pair
    int c16  = lane & 15;       // float4 index within 64-float row (b pair 2c16, 2c16+1)
    int i0   = cta * ROWS_CTA;

    // Wh rows -> SMEM, each value duplicated into a packed pair
    for (int idx = tid; idx < ROWS_CTA * N_HID; idx += TPB) {
        int r = idx >> 10;
        int j = idx & (N_HID - 1);
        unsigned vb = __float_as_uint(Wh[(size_t)(i0 + r) * N_HID + j]);
        wh64[j * 8 + r] = ((u64)vb << 32) | vb;
    }

    // combine thread identity (valid for tid<256): output (row r_, batch b)
    int r_ = tid >> 5;
    int b  = tid & 31;
    int ig = i0 + (r_ & 7);
    float st = 0.f, ci = 1.f, si = 0.f;
    if (tid < 256) gX64[0][ig][b] = pack2(1.f, 0.f);     // cos=1, sin=0
    grid_barrier(tid, cta, 1);

    const int j0 = w * 64;

    for (int t = 0; t < T_STEPS; t++) {
        int cur = t & 1, nxt = cur ^ 1;

        float inp_v = 0.f;
        if (tid < 256)
            inp_v = __ldcg(&g_inp[((size_t)t * N_HID + ig) * BATCH + b]);

        // ---- GEMM: warp w owns j in [64w, 64w+64); lane handles j = j0+2i+jh ----
        const ulonglong2* xp = (const ulonglong2*)&gX64[cur][0][0]
                               + (size_t)(j0 + jh) * 16 + c16;
        u64 acc[16];
#pragma unroll
        for (int k = 0; k < 16; k++) acc[k] = 0ull;

        ulonglong2 xq0 = __ldcg(xp);
        ulonglong2 xq1 = __ldcg(xp + 32);
#pragma unroll 4
        for (int i = 0; i < 32; i++) {
            ulonglong2 xc = xq0;
            xq0 = xq1;
            if (i + 2 < 32) xq1 = __ldcg(xp + (i + 2) * 32);

            int j = j0 + 2 * i + jh;
            const ulonglong2* whp = wh2 + (size_t)j * 4;
            ulonglong2 w0 = whp[0], w1 = whp[1], w2 = whp[2], w3 = whp[3];
            // acc[2r] : b=2c16 ; acc[2r+1] : b=2c16+1 ; each u64 = (Cc, Cs)
            FMA2(acc[ 0], w0.x, xc.x); FMA2(acc[ 1], w0.x, xc.y);
            FMA2(acc[ 2], w0.y, xc.x); FMA2(acc[ 3], w0.y, xc.y);
            FMA2(acc[ 4], w1.x, xc.x); FMA2(acc[ 5], w1.x, xc.y);
            FMA2(acc[ 6], w1.y, xc.x); FMA2(acc[ 7], w1.y, xc.y);
            FMA2(acc[ 8], w2.x, xc.x); FMA2(acc[ 9], w2.x, xc.y);
            FMA2(acc[10], w2.y, xc.x); FMA2(acc[11], w2.y, xc.y);
            FMA2(acc[12], w3.x, xc.x); FMA2(acc[13], w3.x, xc.y);
            FMA2(acc[14], w3.y, xc.x); FMA2(acc[15], w3.y, xc.y);
        }

        // ---- reduce jh pairs within warp (lane += lane+16) ----
#pragma unroll
        for (int k = 0; k < 16; k++) {
            unsigned lo = __shfl_down_sync(0xFFFFFFFFu, (unsigned)acc[k], 16);
            unsigned hi = __shfl_down_sync(0xFFFFFFFFu, (unsigned)(acc[k] >> 32), 16);
            u64 other = ((u64)hi << 32) | lo;
            ADD2(acc[k], other);
        }
        if (jh == 0) {
            int b0 = 2 * c16;
#pragma unroll
            for (int r = 0; r < 8; r++) {
                red[(r * 32 + b0)     * 17 + w] = acc[2 * r];
                red[(r * 32 + b0 + 1) * 17 + w] = acc[2 * r + 1];
            }
        }
        __syncthreads();

        // ---- combine: sum 16 K-slices, update state, next cos/sin ----
        if (tid < 256) {
            const u64* rp = red + (r_ * 32 + b) * 17;
            u64 s0 = rp[0], s1 = rp[1], s2 = rp[2], s3 = rp[3];
            ADD2(s0, rp[4]);  ADD2(s1, rp[5]);  ADD2(s2, rp[6]);  ADD2(s3, rp[7]);
            ADD2(s0, rp[8]);  ADD2(s1, rp[9]);  ADD2(s2, rp[10]); ADD2(s3, rp[11]);
            ADD2(s0, rp[12]); ADD2(s1, rp[13]); ADD2(s2, rp[14]); ADD2(s3, rp[15]);
            ADD2(s0, s1); ADD2(s2, s3); ADD2(s0, s2);
            float Cc = lo32(s0), Cs = hi32(s0);
            float coupling = si * Cc - ci * Cs;
            float v = coupling + inp_v + st;
            float r = fmodf(v, TWO_PI_F);
            if (r < 0.f) r += TWO_PI_F;         // == jnp.remainder(v, 2pi)
            st = r;
            float sn, cn;
            sincosf(r, &sn, &cn);
            ci = cn; si = sn;
            gX64[nxt][ig][b] = pack2(cn, sn);
        }
        grid_barrier(tid, cta, (unsigned)(t + 2));
    }

    // ---- fused readout ----
    float* sst = (float*)red;                   // reuse reduction smem
    if (tid < 256) sst[r_ * 32 + b] = st;       // state for this CTA's 8 rows
    __syncthreads();
    if (tid < BATCH * N_OUT) {                  // 320 threads: (o = tid>>5, b2 = tid&31)
        int o = tid >> 5;
        int b2 = tid & 31;
        float p = 0.f;
#pragma unroll
        for (int r = 0; r < 8; r++)
            p = fmaf(sst[r * 32 + b2], __ldg(&W_out[(size_t)o * N_HID + i0 + r]), p);
        g_rout[(b2 * N_OUT + o) * NCTA + cta] = p;
    }
    grid_barrier(tid, cta, T_STEPS + 2);
    if (cta == 0 && tid < BATCH * N_OUT) {
        int b2 = tid / N_OUT, o = tid % N_OUT;
        const float4* q = (const float4*)(g_rout + (size_t)(b2 * N_OUT + o) * NCTA);
        float a0 = 0.f, a1 = 0.f, a2 = 0.f, a3 = 0.f;
#pragma unroll
        for (int k = 0; k < 32; k++) {
            float4 v = __ldcg(q + k);
            a0 += v.x; a1 += v.y; a2 += v.z; a3 += v.w;
        }
        out[b2 * N_OUT + o] = ((a0 + a1) + (a2 + a3)) + __ldg(b_out + o);
    }
}

// ---------------- launch ----------------------------------------------------
extern "C" void kernel_launch(void* const* d_in, const int* in_sizes, int n_in,
                              void* d_out, int out_size) {
    const float* x     = (const float*)d_in[0];
    const float* Wi_w  = (const float*)d_in[1];
    const float* Wi_b  = (const float*)d_in[2];
    const float* Wh    = (const float*)d_in[3];
    const float* omega = (const float*)d_in[4];
    const float* W_out = (const float*)d_in[5];
    const float* b_out = (const float*)d_in[6];
    float* out = (float*)d_out;

    const int SMEM_BYTES = 65536 + 256 * 17 * 8;   // 100352
    cudaFuncSetAttribute(step_kernel,
                         cudaFuncAttributeMaxDynamicSharedMemorySize, SMEM_BYTES);

    prep_kernel<<<dim3(4, T_STEPS), 256>>>(x, Wi_w, Wi_b, omega);
    step_kernel<<<NCTA, TPB, SMEM_BYTES>>>(Wh, W_out, b_out, out);
}

// round 8
// speedup vs baseline: 1.6095x; 1.0239x over previous
#include <cuda_runtime.h>
#include <cstdint>

#define T_STEPS   256
#define BATCH     32
#define N_INP     28
#define N_HID     1024
#define N_OUT     10
#define NCTA      128
#define N_RT      64         // row tiles
#define ROWS_CTA  16         // rows per CTA
#define B_CTA     16         // batches per CTA
#define TPB       512        // 16 warps, warp w owns 64 j
#define TWO_PI_F  6.283185307179586f

typedef unsigned long long u64;

// ---------------- device globals ----------------
__device__ float g_inp[T_STEPS * N_HID * BATCH];            // [t][h][b]
__device__ __align__(256) u64 gX64[2][N_HID][BATCH];        // [buf][j][b] = pack(cos, sin)
__device__ unsigned g_flags[NCTA * 8];                      // 32B-spread arrival flags
__device__ float g_rout[BATCH * N_OUT * N_RT];              // readout partials

// packed f32x2 ops
#define FMA2(acc, a, b) \
    asm("fma.rn.f32x2 %0, %1, %2, %0;" : "+l"(acc) : "l"(a), "l"(b))
#define ADD2(acc, b) \
    asm("add.rn.f32x2 %0, %0, %1;" : "+l"(acc) : "l"(b))

__device__ __forceinline__ u64 pack2(float lo, float hi) {
    u64 r;
    asm("mov.b64 %0, {%1, %2};" : "=l"(r) : "f"(lo), "f"(hi));
    return r;
}
__device__ __forceinline__ float lo32(u64 v) { return __uint_as_float((unsigned)v); }
__device__ __forceinline__ float hi32(u64 v) { return __uint_as_float((unsigned)(v >> 32)); }

// ---------------- grid barrier: per-CTA flag + distributed poll -------------
__device__ __forceinline__ void grid_barrier(int tid, int cta, unsigned target) {
    __syncthreads();
    if (tid < 32) {
        if (tid == 0) {
            asm volatile("st.global.release.gpu.u32 [%0], %1;"
                         :: "l"(&g_flags[cta * 8]), "r"(target) : "memory");
        }
        const unsigned* p0 = &g_flags[(tid +  0) * 8];
        const unsigned* p1 = &g_flags[(tid + 32) * 8];
        const unsigned* p2 = &g_flags[(tid + 64) * 8];
        const unsigned* p3 = &g_flags[(tid + 96) * 8];
        unsigned f0, f1, f2, f3;
        bool pending;
        do {
            asm volatile("ld.global.acquire.gpu.u32 %0, [%1];" : "=r"(f0) : "l"(p0) : "memory");
            asm volatile("ld.global.acquire.gpu.u32 %0, [%1];" : "=r"(f1) : "l"(p1) : "memory");
            asm volatile("ld.global.acquire.gpu.u32 %0, [%1];" : "=r"(f2) : "l"(p2) : "memory");
            asm volatile("ld.global.acquire.gpu.u32 %0, [%1];" : "=r"(f3) : "l"(p3) : "memory");
            pending = (f0 < target) | (f1 < target) | (f2 < target) | (f3 < target);
        } while (__any_sync(0xFFFFFFFFu, pending));
    }
    __syncthreads();
}

// ---------------- kernel A: input projection + flag reset -------------------
__global__ void __launch_bounds__(256)
prep_kernel(const float* __restrict__ x,
            const float* __restrict__ Wi_w,
            const float* __restrict__ Wi_b,
            const float* __restrict__ omega) {
    int t   = blockIdx.y;
    int hg  = blockIdx.x;
    int tid = threadIdx.x;
    int w   = tid >> 5;
    int b   = tid & 31;

    if (t == 0 && hg == 0 && tid < NCTA) g_flags[tid * 8] = 0;

    float4 xq[7];
    const float4* xrow = (const float4*)(x + (size_t)t * BATCH * N_INP + b * N_INP);
#pragma unroll
    for (int q = 0; q < 7; q++) xq[q] = xrow[q];

    int h0 = hg * 256 + w * 32;
    for (int hh = 0; hh < 32; hh++) {
        int h = h0 + hh;
        const float4* wr = (const float4*)(Wi_w + (size_t)h * N_INP);
        float acc = __ldg(Wi_b + h) + __ldg(omega + h);
#pragma unroll
        for (int q = 0; q < 7; q++) {
            float4 wv = __ldg(wr + q);
            acc = fmaf(wv.x, xq[q].x, acc);
            acc = fmaf(wv.y, xq[q].y, acc);
            acc = fmaf(wv.z, xq[q].z, acc);
            acc = fmaf(wv.w, xq[q].w, acc);
        }
        g_inp[((size_t)t * N_HID + h) * BATCH + b] = acc;
    }
}

// ---------------- kernel B: persistent scan + fused readout -----------------
// SMEM: [0,128K) wh64[j][16 rows] dup pairs ; [128K,+32K) red[w][r*16+b] u64
extern __shared__ unsigned char smem_raw[];

__global__ void __launch_bounds__(TPB, 1)
step_kernel(const float* __restrict__ Wh,
            const float* __restrict__ W_out,
            const float* __restrict__ b_out,
            float* __restrict__ out) {
    u64* wh64 = (u64*)smem_raw;                          // [j*16 + r] dup pairs
    u64* red  = (u64*)(smem_raw + 131072);               // [w*256 + r*16 + b]

    int tid  = threadIdx.x;
    int cta  = blockIdx.x;
    int w    = tid >> 5;        // 0..15
    int lane = tid & 31;
    int rg4  = lane >> 3;       // 4 row-groups of 4 rows
    int bp   = lane & 7;        // 8 b-pairs of 2 b
    int rt   = cta >> 1;        // row tile 0..63
    int bt   = cta & 1;         // batch tile 0..1
    int i0   = rt * ROWS_CTA;   // first row
    int b0   = bt * B_CTA;      // first batch

    // Wh rows -> SMEM (transposed, dup-paired): wh64[j*16+r] = dup(Wh[i0+r][j])
    for (int idx = tid; idx < ROWS_CTA * N_HID; idx += TPB) {
        int j = idx & (N_HID - 1);
        int r = idx >> 10;
        unsigned vb = __float_as_uint(Wh[(size_t)(i0 + r) * N_HID + j]);
        wh64[j * 16 + r] = ((u64)vb << 32) | vb;
    }

    // combine thread identity (tid<256): output (row r_, batch bl)
    int r_ = tid >> 4;          // 0..15
    int bl = tid & 15;          // 0..15
    int ig = i0 + (r_ & 15);
    int bg = b0 + bl;
    float st = 0.f, ci = 1.f, si = 0.f;
    if (tid < 256) gX64[0][ig][bg] = pack2(1.f, 0.f);    // cos=1, sin=0
    grid_barrier(tid, cta, 1);

    const int j0 = w * 64;
    const ulonglong2* wh_base = (const ulonglong2*)(wh64 + (size_t)j0 * 16 + rg4 * 4);

    for (int t = 0; t < T_STEPS; t++) {
        int cur = t & 1, nxt = cur ^ 1;

        float inp_v = 0.f;
        if (tid < 256)
            inp_v = __ldcg(&g_inp[((size_t)t * N_HID + ig) * BATCH + bg]);

        // ---- GEMM: warp w owns j in [64w, 64w+64) ----
        // lane loads X[j][b0+2bp..+1] (16B), Wh dup for rows 4rg4..+3 (2x16B)
        const ulonglong2* xp = (const ulonglong2*)&gX64[cur][j0][b0 + 2 * bp];
        u64 acc[8];
#pragma unroll
        for (int k = 0; k < 8; k++) acc[k] = 0ull;

        ulonglong2 xq[4];
        xq[0] = __ldcg(xp);
        xq[1] = __ldcg(xp + 16);
        xq[2] = __ldcg(xp + 32);
        xq[3] = __ldcg(xp + 48);
#pragma unroll 4
        for (int i = 0; i < 64; i++) {
            ulonglong2 xc = xq[i & 3];
            if (i + 4 < 64) xq[i & 3] = __ldcg(xp + (i + 4) * 16);

            ulonglong2 wA = wh_base[i * 8];       // dup rows 4rg4, 4rg4+1
            ulonglong2 wB = wh_base[i * 8 + 1];   // dup rows 4rg4+2, 4rg4+3
            // acc[rr*2+bb] = (Cc,Cs) for row 4rg4+rr, batch b0+2bp+bb
            FMA2(acc[0], wA.x, xc.x); FMA2(acc[1], wA.x, xc.y);
            FMA2(acc[2], wA.y, xc.x); FMA2(acc[3], wA.y, xc.y);
            FMA2(acc[4], wB.x, xc.x); FMA2(acc[5], wB.x, xc.y);
            FMA2(acc[6], wB.y, xc.x); FMA2(acc[7], wB.y, xc.y);
        }

        // ---- partials to SMEM: red[w*256 + row*16 + b] ----
        {
            u64* rw = red + (size_t)w * 256 + (rg4 * 4) * 16 + 2 * bp;
#pragma unroll
            for (int rr = 0; rr < 4; rr++) {
                ulonglong2 v;
                v.x = acc[rr * 2];
                v.y = acc[rr * 2 + 1];
                *(ulonglong2*)(rw + rr * 16) = v;
            }
        }
        __syncthreads();

        // ---- combine: sum 16 K-slices, update state, next cos/sin ----
        if (tid < 256) {
            const u64* rp = red + tid;            // r_*16+bl == tid
            u64 s0 = rp[0],        s1 = rp[256],  s2 = rp[512],  s3 = rp[768];
            ADD2(s0, rp[1024]); ADD2(s1, rp[1280]); ADD2(s2, rp[1536]); ADD2(s3, rp[1792]);
            ADD2(s0, rp[2048]); ADD2(s1, rp[2304]); ADD2(s2, rp[2560]); ADD2(s3, rp[2816]);
            ADD2(s0, rp[3072]); ADD2(s1, rp[3328]); ADD2(s2, rp[3584]); ADD2(s3, rp[3840]);
            ADD2(s0, s1); ADD2(s2, s3); ADD2(s0, s2);
            float Cc = lo32(s0), Cs = hi32(s0);
            float coupling = si * Cc - ci * Cs;
            float v = coupling + inp_v + st;
            float r = fmodf(v, TWO_PI_F);
            if (r < 0.f) r += TWO_PI_F;           // == jnp.remainder(v, 2pi)
            st = r;
            float sn, cn;
            sincosf(r, &sn, &cn);
            ci = cn; si = sn;
            gX64[nxt][ig][bg] = pack2(cn, sn);
        }
        grid_barrier(tid, cta, (unsigned)(t + 2));
    }

    // ---- fused readout ----
    float* sst = (float*)red;                     // reuse reduction smem
    if (tid < 256) sst[tid] = st;                 // [r_*16 + bl]
    __syncthreads();
    if (tid < B_CTA * N_OUT) {                    // 160 threads: o = tid/16, b = tid%16
        int o  = tid >> 4;
        int b2 = tid & 15;
        float p = 0.f;
#pragma unroll
        for (int r = 0; r < ROWS_CTA; r++)
            p = fmaf(sst[r * 16 + b2], __ldg(&W_out[(size_t)o * N_HID + i0 + r]), p);
        g_rout[((b0 + b2) * N_OUT + o) * N_RT + rt] = p;
    }
    grid_barrier(tid, cta, T_STEPS + 2);
    if (cta == 0 && tid < BATCH * N_OUT) {
        int b2 = tid / N_OUT, o = tid % N_OUT;
        const float4* q = (const float4*)(g_rout + (size_t)(b2 * N_OUT + o) * N_RT);
        float a0 = 0.f, a1 = 0.f, a2 = 0.f, a3 = 0.f;
#pragma unroll
        for (int k = 0; k < 16; k++) {
            float4 v = __ldcg(q + k);
            a0 += v.x; a1 += v.y; a2 += v.z; a3 += v.w;
        }
        out[b2 * N_OUT + o] = ((a0 + a1) + (a2 + a3)) + __ldg(b_out + o);
    }
}

// ---------------- launch ----------------------------------------------------
extern "C" void kernel_launch(void* const* d_in, const int* in_sizes, int n_in,
                              void* d_out, int out_size) {
    const float* x     = (const float*)d_in[0];
    const float* Wi_w  = (const float*)d_in[1];
    const float* Wi_b  = (const float*)d_in[2];
    const float* Wh    = (const float*)d_in[3];
    const float* omega = (const float*)d_in[4];
    const float* W_out = (const float*)d_in[5];
    const float* b_out = (const float*)d_in[6];
    float* out = (float*)d_out;

    const int SMEM_BYTES = 131072 + 32768;   // Wh dup (128K) + red (32K)
    cudaFuncSetAttribute(step_kernel,
                         cudaFuncAttributeMaxDynamicSharedMemorySize, SMEM_BYTES);

    prep_kernel<<<dim3(4, T_STEPS), 256>>>(x, Wi_w, Wi_b, omega);
    step_kernel<<<NCTA, TPB, SMEM_BYTES>>>(Wh, W_out, b_out, out);
}